// round 5
// baseline (speedup 1.0000x reference)
#include <cuda_runtime.h>

#define HEADS 4
#define DIM   64
#define BB    8
#define QQ    128
#define VV    128
#define NN    (BB*QQ)   // 1024

typedef unsigned long long ull;

// Scratch (device globals — no allocation allowed). g_VU has one row of pad
// so the recurrence can prefetch one step past the end unconditionally.
__device__ float2 g_QU[HEADS * NN * DIM];                 // [h][n][j] complex
__device__ float2 g_VU[HEADS * BB * VV * DIM + DIM];      // [h][b][v][j] complex (+pad)
__device__ float  g_acc[NN * HEADS * DIM];                // [n][h*64+j] real

// ---------------------------------------------------------------------------
// f32x2 packed helpers (Blackwell sm_103a)
// ---------------------------------------------------------------------------
__device__ __forceinline__ ull pk(float lo, float hi) {
    ull d; asm("mov.b64 %0,{%1,%2};" : "=l"(d) : "f"(lo), "f"(hi)); return d;
}
__device__ __forceinline__ float lo32(ull a) {
    float x; asm("{ .reg .b32 t; mov.b64 {%0,t},%1; }" : "=f"(x) : "l"(a)); return x;
}
__device__ __forceinline__ float hi32(ull a) {
    float x; asm("{ .reg .b32 t; mov.b64 {t,%0},%1; }" : "=f"(x) : "l"(a)); return x;
}
__device__ __forceinline__ ull swp(ull a) {
    ull d; asm("{ .reg .b32 lo,hi; mov.b64 {lo,hi},%1; mov.b64 %0,{hi,lo}; }"
               : "=l"(d) : "l"(a)); return d;
}
__device__ __forceinline__ ull fma2(ull a, ull b, ull c) {
    ull d; asm("fma.rn.f32x2 %0,%1,%2,%3;" : "=l"(d) : "l"(a), "l"(b), "l"(c)); return d;
}
__device__ __forceinline__ ull mul2(ull a, ull b) {
    ull d; asm("mul.rn.f32x2 %0,%1,%2;" : "=l"(d) : "l"(a), "l"(b)); return d;
}
__device__ __forceinline__ ull add2(ull a, ull b) {
    ull d; asm("add.rn.f32x2 %0,%1,%2;" : "=l"(d) : "l"(a), "l"(b)); return d;
}
__device__ __forceinline__ float sqrt_apx(float s) {
    float r; asm("sqrt.approx.f32 %0,%1;" : "=f"(r) : "f"(s)); return r;
}
__device__ __forceinline__ float rcp_apx(float s) {
    float r; asm("rcp.approx.f32 %0,%1;" : "=f"(r) : "f"(s)); return r;
}

// ---------------------------------------------------------------------------
// Kernel 1 (tiled GEMM): for part p (0:queries->g_QU, 1:values->g_VU), head h,
// row-tile of 64 rows:  out[row, j] = sum_k x[row,k] * U[h, p*64+k, j]  (complex)
// Block: 256 threads. smem: x tile 16KB + U re/im 32KB = 48KB.
// Thread t: j0=t&31, j1=j0+32, rg=t>>5 -> rows rg*8 .. rg*8+7.
// ---------------------------------------------------------------------------
__global__ void __launch_bounds__(256) k_compute_u(
    const float* __restrict__ q,      // [1024,64]
    const float* __restrict__ vals,   // [1024,64]
    const float* __restrict__ Ure,    // [4,128,64]
    const float* __restrict__ Uim)
{
    __shared__ float x_s[64 * 64];    // [r][k]
    __shared__ float ur_s[64 * 64];   // [k][j]
    __shared__ float ui_s[64 * 64];

    int t    = threadIdx.x;
    int tile = blockIdx.x & 15;
    int p    = (blockIdx.x >> 4) & 1;
    int h    = blockIdx.x >> 5;

    // stage x tile (64 rows x 64 cols)
    const float4* src4 = (const float4*)((p == 0 ? q : vals) + tile * 64 * 64);
    float4* xs4 = (float4*)x_s;
    #pragma unroll
    for (int i = 0; i < 4; i++) xs4[t + 256 * i] = __ldg(src4 + t + 256 * i);

    // stage U tiles (64 k x 64 j, re and im)
    const float4* ur4 = (const float4*)(Ure + h * 8192 + p * 4096);
    const float4* ui4 = (const float4*)(Uim + h * 8192 + p * 4096);
    float4* urs4 = (float4*)ur_s;
    float4* uis4 = (float4*)ui_s;
    #pragma unroll
    for (int i = 0; i < 4; i++) {
        urs4[t + 256 * i] = __ldg(ur4 + t + 256 * i);
        uis4[t + 256 * i] = __ldg(ui4 + t + 256 * i);
    }
    __syncthreads();

    int j0 = t & 31, j1 = j0 + 32, rg = t >> 5;

    float a0r[8], a0i[8], a1r[8], a1i[8];
    #pragma unroll
    for (int i = 0; i < 8; i++) { a0r[i] = a0i[i] = a1r[i] = a1i[i] = 0.f; }

    #pragma unroll 4
    for (int k = 0; k < 64; k++) {
        float u0r = ur_s[k * 64 + j0];
        float u1r = ur_s[k * 64 + j1];
        float u0i = ui_s[k * 64 + j0];
        float u1i = ui_s[k * 64 + j1];
        #pragma unroll
        for (int i = 0; i < 8; i++) {
            float xv = x_s[(rg * 8 + i) * 64 + k];
            a0r[i] = fmaf(xv, u0r, a0r[i]);
            a0i[i] = fmaf(xv, u0i, a0i[i]);
            a1r[i] = fmaf(xv, u1r, a1r[i]);
            a1i[i] = fmaf(xv, u1i, a1i[i]);
        }
    }

    float2* dst = (p == 0 ? g_QU : g_VU) + (size_t)h * NN * DIM + (size_t)tile * 64 * DIM;
    #pragma unroll
    for (int i = 0; i < 8; i++) {
        int row = rg * 8 + i;
        dst[row * DIM + j0] = make_float2(a0r[i], a0i[i]);
        dst[row * DIM + j1] = make_float2(a1r[i], a1i[i]);
    }
}

// ---------------------------------------------------------------------------
// Kernel 2: EUNN+modrelu recurrence, f32x2 packed. One warp per (h, n).
// Lane l owns complex elems 2l (A) and 2l+1 (B), each packed as (re, im).
// ---------------------------------------------------------------------------
__global__ void __launch_bounds__(512) k_recur(
    const float* __restrict__ bias,   // [4,64]
    const float* __restrict__ th1,    // [4,32]
    const float* __restrict__ ph1,    // [4,32]
    const float* __restrict__ th2,    // [4,31]
    const float* __restrict__ ph2,    // [4,31]
    const float* __restrict__ om)     // [4,64]
{
    const unsigned FULL = 0xffffffffu;
    int w = (blockIdx.x * blockDim.x + threadIdx.x) >> 5;   // 0..4095
    int l = threadIdx.x & 31;
    int h = w >> 10;
    int n = w & (NN - 1);
    int b = n >> 7;

    float c1, s1, e1r, e1i;
    sincosf(th1[h * 32 + l], &s1, &c1);
    sincosf(ph1[h * 32 + l], &e1i, &e1r);

    float c2 = 1.f, s2 = 0.f, e2r = 1.f, e2i = 0.f;
    if (l < 31) {
        sincosf(th2[h * 31 + l], &s2, &c2);
        sincosf(ph2[h * 31 + l], &e2i, &e2r);
    }
    float c2p = 1.f, s2p = 0.f;
    if (l > 0) sincosf(th2[h * 31 + l - 1], &s2p, &c2p);

    float omAr, omAi, omBr, omBi;
    sincosf(om[h * 64 + 2 * l],     &omAi, &omAr);
    sincosf(om[h * 64 + 2 * l + 1], &omBi, &omBr);
    float bA = bias[h * 64 + 2 * l];
    float bB = bias[h * 64 + 2 * l + 1];

    // packed per-lane constants
    ull c1_2  = pk(c1, c1),    s1_2  = pk(s1, s1),   ns1_2 = pk(-s1, -s1);
    ull e1r_2 = pk(e1r, e1r),  e1pm  = pk(-e1i, e1i);
    ull c2_2  = pk(c2, c2),    ns2_2 = pk(-s2, -s2);
    ull e2r_2 = pk(e2r, e2r),  e2pm  = pk(-e2i, e2i);
    ull c2p_2 = pk(c2p, c2p),  s2p_2 = pk(s2p, s2p);
    ull omAr_2 = pk(omAr, omAr), omApm = pk(-omAi, omAi);
    ull omBr_2 = pk(omBr, omBr), omBpm = pk(-omBi, omBi);

    float4 qu = __ldg((const float4*)&g_QU[(h * NN + n) * DIM + 2 * l]);
    ull quA = pk(qu.x, qu.y), quB = pk(qu.z, qu.w);
    const float4* vup = (const float4*)&g_VU[((h * BB + b) * VV) * DIM + 2 * l];

    ull A = 0ull, B = 0ull;

    float4 vu = __ldg(vup); vup += DIM / 2;   // prefetch step 0

    #pragma unroll 2
    for (int v = 0; v < VV; v++) {
        float4 vun = __ldg(vup); vup += DIM / 2;   // prefetch next (pad covers v=127)

        ull vuA = pk(vu.x, vu.y), vuB = pk(vu.z, vu.w);
        ull inA = add2(quA, vuA);
        ull inB = add2(quB, vuB);

        // EUNN layer 1: pair (2l, 2l+1)
        ull tA = fma2(c1_2, A, mul2(ns1_2, B));    // c1*A - s1*B
        ull nB = fma2(s1_2, A, mul2(c1_2, B));     // s1*A + c1*B
        ull nA = fma2(e1pm, swp(tA), mul2(e1r_2, tA));  // e1 * tA (complex)

        // cross-lane exchange for layer 2
        ull xu = __shfl_up_sync(FULL, nB, 1);      // nB of lane l-1
        ull xd = __shfl_down_sync(FULL, nA, 1);    // nA of lane l+1

        // layer 2
        ull t2 = fma2(c2_2, nB, mul2(ns2_2, xd));       // c2*nB - s2*nA_next
        ull oB = fma2(e2pm, swp(t2), mul2(e2r_2, t2));  // e2 * t2 (complex)
        ull oA = fma2(s2p_2, xu, mul2(c2p_2, nA));      // s2p*nB_prev + c2p*nA

        // diagonal phase + input
        ull zA = add2(fma2(omApm, swp(oA), mul2(omAr_2, oA)), inA);
        ull zB = add2(fma2(omBpm, swp(oB), mul2(omBr_2, oB)), inB);

        // modrelu
        float zAr = lo32(zA), zAi = hi32(zA);
        float sA = fmaf(zAi, zAi, zAr * zAr);
        float mA = sqrt_apx(sA);
        float scA = fmaxf(mA + bA, 0.f) * rcp_apx(mA + 1e-5f);
        A = mul2(pk(scA, scA), zA);

        float zBr = lo32(zB), zBi = hi32(zB);
        float sB = fmaf(zBi, zBi, zBr * zBr);
        float mB = sqrt_apx(sB);
        float scB = fmaxf(mB + bB, 0.f) * rcp_apx(mB + 1e-5f);
        B = mul2(pk(scB, scB), zB);

        vu = vun;
    }

    float2* accp = (float2*)&g_acc[n * (HEADS * DIM) + h * DIM + 2 * l];
    *accp = make_float2(lo32(A), lo32(B));
}

// ---------------------------------------------------------------------------
// Kernel 3: y = acc @ W + b   ([1024,256] @ [256,64])
// 64 blocks x 256 threads; block handles 16 rows. Thread (ty=t>>4, tx=t&15)
// computes row ty, cols 4tx..4tx+3. acc staged in smem with stride 264.
// ---------------------------------------------------------------------------
#define AST 264
__global__ void __launch_bounds__(256) k_proj(
    const float* __restrict__ W,    // [256,64]
    const float* __restrict__ bd,   // [64]
    float* __restrict__ out)        // [1024,64]
{
    __shared__ float a_s[16 * AST];
    int t = threadIdx.x;
    int row0 = blockIdx.x * 16;

    // stage 16 rows x 256 cols of g_acc
    const float4* g4 = (const float4*)(g_acc + row0 * 256);
    #pragma unroll
    for (int i = 0; i < 4; i++) {
        int g = t + 256 * i;            // float4 index; 64 float4 per row
        int r = g >> 6, c4 = g & 63;
        *(float4*)&a_s[r * AST + c4 * 4] = __ldg(g4 + g);
    }
    __syncthreads();

    int tx = t & 15, ty = t >> 4;
    float4 s = __ldg((const float4*)(bd + 4 * tx));
    const float* arow = a_s + ty * AST;

    #pragma unroll 4
    for (int k = 0; k < 256; k++) {
        float a = arow[k];
        float4 wv = __ldg((const float4*)(W + k * 64 + 4 * tx));
        s.x = fmaf(a, wv.x, s.x);
        s.y = fmaf(a, wv.y, s.y);
        s.z = fmaf(a, wv.z, s.z);
        s.w = fmaf(a, wv.w, s.w);
    }
    *(float4*)(out + (row0 + ty) * 64 + 4 * tx) = s;
}

// ---------------------------------------------------------------------------
extern "C" void kernel_launch(void* const* d_in, const int* in_sizes, int n_in,
                              void* d_out, int out_size)
{
    const float* queries = (const float*)d_in[0];
    const float* values  = (const float*)d_in[1];
    const float* U_re    = (const float*)d_in[2];
    const float* U_im    = (const float*)d_in[3];
    const float* bias    = (const float*)d_in[4];
    const float* theta1  = (const float*)d_in[5];
    const float* phi1    = (const float*)d_in[6];
    const float* theta2  = (const float*)d_in[7];
    const float* phi2    = (const float*)d_in[8];
    const float* omega   = (const float*)d_in[9];
    const float* W_dense = (const float*)d_in[10];
    const float* b_dense = (const float*)d_in[11];
    float* out = (float*)d_out;

    k_compute_u<<<128, 256>>>(queries, values, U_re, U_im);
    k_recur<<<256, 512>>>(bias, theta1, phi1, theta2, phi2, omega);
    k_proj<<<64, 256>>>(W_dense, b_dense, out);
}

// round 6
// speedup vs baseline: 1.2566x; 1.2566x over previous
#include <cuda_runtime.h>

#define HEADS 4
#define DIM   64
#define BB    8
#define QQ    128
#define VV    128
#define NN    (BB*QQ)   // 1024

// Scratch (device globals — no allocation allowed). g_VU has one row of pad
// so the recurrence can prefetch one step past the end unconditionally.
__device__ float2 g_QU[HEADS * NN * DIM];                 // [h][n][j] complex
__device__ float2 g_VU[HEADS * BB * VV * DIM + DIM];      // [h][b][v][j] complex (+pad)
__device__ float  g_acc[NN * HEADS * DIM];                // [n][h*64+j] real

__device__ __forceinline__ float sqrt_apx(float s) {
    float r; asm("sqrt.approx.f32 %0,%1;" : "=f"(r) : "f"(s)); return r;
}
__device__ __forceinline__ float rcp_apx(float s) {
    float r; asm("rcp.approx.f32 %0,%1;" : "=f"(r) : "f"(s)); return r;
}

// ---------------------------------------------------------------------------
// Kernel 1 (tiled GEMM): for part p (0:queries->g_QU, 1:values->g_VU), head h,
// 32-row tile:  out[row, j] = sum_k x[row,k] * U[h, p*64+k, j]  (complex)
// grid = 4 heads * 2 parts * 32 tiles = 256 blocks, 256 threads.
// smem: x 8KB + U re/im 32KB = 40KB -> 2 blocks/SM resident.
// Thread t: j0=t&31, j1=j0+32, rg=t>>5 -> rows rg*4 .. rg*4+3.
// ---------------------------------------------------------------------------
__global__ void __launch_bounds__(256) k_compute_u(
    const float* __restrict__ q,      // [1024,64]
    const float* __restrict__ vals,   // [1024,64]
    const float* __restrict__ Ure,    // [4,128,64]
    const float* __restrict__ Uim)
{
    __shared__ float x_s[32 * 64];    // [r][k]
    __shared__ float ur_s[64 * 64];   // [k][j]
    __shared__ float ui_s[64 * 64];

    int t    = threadIdx.x;
    int tile = blockIdx.x & 31;
    int p    = (blockIdx.x >> 5) & 1;
    int h    = blockIdx.x >> 6;

    // stage x tile (32 rows x 64 cols) = 512 float4
    const float4* src4 = (const float4*)((p == 0 ? q : vals) + tile * 32 * 64);
    float4* xs4 = (float4*)x_s;
    #pragma unroll
    for (int i = 0; i < 2; i++) xs4[t + 256 * i] = __ldg(src4 + t + 256 * i);

    // stage U tiles (64 k x 64 j, re and im) = 1024 float4 each
    const float4* ur4 = (const float4*)(Ure + h * 8192 + p * 4096);
    const float4* ui4 = (const float4*)(Uim + h * 8192 + p * 4096);
    float4* urs4 = (float4*)ur_s;
    float4* uis4 = (float4*)ui_s;
    #pragma unroll
    for (int i = 0; i < 4; i++) {
        urs4[t + 256 * i] = __ldg(ur4 + t + 256 * i);
        uis4[t + 256 * i] = __ldg(ui4 + t + 256 * i);
    }
    __syncthreads();

    int j0 = t & 31, j1 = j0 + 32, rg = t >> 5;

    float a0r[4], a0i[4], a1r[4], a1i[4];
    #pragma unroll
    for (int i = 0; i < 4; i++) { a0r[i] = a0i[i] = a1r[i] = a1i[i] = 0.f; }

    #pragma unroll 8
    for (int k = 0; k < 64; k++) {
        float u0r = ur_s[k * 64 + j0];
        float u1r = ur_s[k * 64 + j1];
        float u0i = ui_s[k * 64 + j0];
        float u1i = ui_s[k * 64 + j1];
        #pragma unroll
        for (int i = 0; i < 4; i++) {
            float xv = x_s[(rg * 4 + i) * 64 + k];   // broadcast within warp
            a0r[i] = fmaf(xv, u0r, a0r[i]);
            a0i[i] = fmaf(xv, u0i, a0i[i]);
            a1r[i] = fmaf(xv, u1r, a1r[i]);
            a1i[i] = fmaf(xv, u1i, a1i[i]);
        }
    }

    float2* dst = (p == 0 ? g_QU : g_VU) + (size_t)h * NN * DIM + (size_t)tile * 32 * DIM;
    #pragma unroll
    for (int i = 0; i < 4; i++) {
        int row = rg * 4 + i;
        dst[row * DIM + j0] = make_float2(a0r[i], a0i[i]);
        dst[row * DIM + j1] = make_float2(a1r[i], a1i[i]);
    }
}

// ---------------------------------------------------------------------------
// Kernel 2: EUNN+modrelu recurrence, scalar with folded constants.
// One warp per (h, n). Lane l owns complex elems 2l (A) and 2l+1 (B).
//   nA = e1*(c1*A - s1*B)            (layer1 'a' output, elem 2l)
//   nB = s1*A + c1*B                 (layer1 'b' output, elem 2l+1)
//   zB = E*(c2*nB - s2*nA_next) + in,  E = e^{i(wB+phi2_l)}   (l=31: c2=1,s2=0,E=e^{iwB})
//   zA = G*nA + F*xu + in,  G = e^{iwA}*c2p, F = e^{iwA}*s2p  (l=0: F=0, G=e^{iwA})
//   modrelu: sc = max(1 + (b-1e-5)*rcp(|z|+1e-5), 0);  h = z*sc
// ---------------------------------------------------------------------------
__global__ void __launch_bounds__(512) k_recur(
    const float* __restrict__ bias,   // [4,64]
    const float* __restrict__ th1,    // [4,32]
    const float* __restrict__ ph1,    // [4,32]
    const float* __restrict__ th2,    // [4,31]
    const float* __restrict__ ph2,    // [4,31]
    const float* __restrict__ om)     // [4,64]
{
    const unsigned FULL = 0xffffffffu;
    int w = (blockIdx.x * blockDim.x + threadIdx.x) >> 5;   // 0..4095
    int l = threadIdx.x & 31;
    int h = w >> 10;
    int n = w & (NN - 1);
    int b = n >> 7;

    // layer-1 constants
    float c1, s1, e1r, e1i;
    sincosf(th1[h * 32 + l], &s1, &c1);
    sincosf(ph1[h * 32 + l], &e1i, &e1r);

    // layer-2 constants (pair l couples elems 2l+1, 2l+2)
    float c2 = 1.f, s2 = 0.f, p2 = 0.f;
    if (l < 31) {
        sincosf(th2[h * 31 + l], &s2, &c2);
        p2 = ph2[h * 31 + l];
    }
    float c2p = 1.f, s2p = 0.f;
    if (l > 0) sincosf(th2[h * 31 + l - 1], &s2p, &c2p);

    float omA = om[h * 64 + 2 * l];
    float omB = om[h * 64 + 2 * l + 1];

    // folded: E = e^{i(omB + phi2_l)}; G = e^{i omA} * c2p; F = e^{i omA} * s2p
    float Er, Ei;
    sincosf(omB + p2, &Ei, &Er);
    float cA_, sA_;
    sincosf(omA, &sA_, &cA_);
    float Gr = c2p * cA_, Gi = c2p * sA_;
    float Fr = s2p * cA_, Fi = s2p * sA_;

    float bAp = bias[h * 64 + 2 * l]     - 1e-5f;
    float bBp = bias[h * 64 + 2 * l + 1] - 1e-5f;

    // per-warp constant input (QU) and per-step VU stream
    float4 qu = __ldg((const float4*)&g_QU[(h * NN + n) * DIM + 2 * l]);
    const float4* vup = (const float4*)&g_VU[((h * BB + b) * VV) * DIM + 2 * l];

    float Ar = 0.f, Ai = 0.f, Br = 0.f, Bi = 0.f;

    float4 vu = __ldg(vup); vup += DIM / 2;   // prefetch step 0

    #pragma unroll 2
    for (int v = 0; v < VV; v++) {
        float4 vun = __ldg(vup); vup += DIM / 2;   // prefetch next (pad covers v=127)

        float inAr = qu.x + vu.x, inAi = qu.y + vu.y;
        float inBr = qu.z + vu.z, inBi = qu.w + vu.w;

        // layer 1
        float tAr = c1 * Ar - s1 * Br;
        float tAi = c1 * Ai - s1 * Bi;
        float nBr = s1 * Ar + c1 * Br;
        float nBi = s1 * Ai + c1 * Bi;
        float nAr = e1r * tAr - e1i * tAi;
        float nAi = e1r * tAi + e1i * tAr;

        // cross-lane exchange
        float xur = __shfl_up_sync(FULL, nBr, 1);     // nB of lane l-1
        float xui = __shfl_up_sync(FULL, nBi, 1);
        float xdr = __shfl_down_sync(FULL, nAr, 1);   // nA of lane l+1
        float xdi = __shfl_down_sync(FULL, nAi, 1);

        // B path: layer2 + phase + input, folded
        float t2r = c2 * nBr - s2 * xdr;
        float t2i = c2 * nBi - s2 * xdi;
        float zBr = fmaf(Er, t2r, fmaf(-Ei, t2i, inBr));
        float zBi = fmaf(Er, t2i, fmaf( Ei, t2r, inBi));

        // A path: layer2 + phase + input, folded
        float zAr = fmaf(Gr, nAr, fmaf(-Gi, nAi, fmaf(Fr, xur, fmaf(-Fi, xui, inAr))));
        float zAi = fmaf(Gr, nAi, fmaf( Gi, nAr, fmaf(Fr, xui, fmaf( Fi, xur, inAi))));

        // modrelu A
        float sA = fmaf(zAi, zAi, zAr * zAr);
        float mA = sqrt_apx(sA);
        float rA = rcp_apx(mA + 1e-5f);
        float scA = fmaxf(fmaf(bAp, rA, 1.0f), 0.0f);
        Ar = zAr * scA; Ai = zAi * scA;

        // modrelu B
        float sB = fmaf(zBi, zBi, zBr * zBr);
        float mB = sqrt_apx(sB);
        float rB = rcp_apx(mB + 1e-5f);
        float scB = fmaxf(fmaf(bBp, rB, 1.0f), 0.0f);
        Br = zBr * scB; Bi = zBi * scB;

        vu = vun;
    }

    float2* accp = (float2*)&g_acc[n * (HEADS * DIM) + h * DIM + 2 * l];
    *accp = make_float2(Ar, Br);
}

// ---------------------------------------------------------------------------
// Kernel 3: y = acc @ W + b   ([1024,256] @ [256,64])
// ---------------------------------------------------------------------------
#define AST 264
__global__ void __launch_bounds__(256) k_proj(
    const float* __restrict__ W,    // [256,64]
    const float* __restrict__ bd,   // [64]
    float* __restrict__ out)        // [1024,64]
{
    __shared__ float a_s[16 * AST];
    int t = threadIdx.x;
    int row0 = blockIdx.x * 16;

    const float4* g4 = (const float4*)(g_acc + row0 * 256);
    #pragma unroll
    for (int i = 0; i < 4; i++) {
        int g = t + 256 * i;
        int r = g >> 6, c4 = g & 63;
        *(float4*)&a_s[r * AST + c4 * 4] = __ldg(g4 + g);
    }
    __syncthreads();

    int tx = t & 15, ty = t >> 4;
    float4 s = __ldg((const float4*)(bd + 4 * tx));
    const float* arow = a_s + ty * AST;

    #pragma unroll 4
    for (int k = 0; k < 256; k++) {
        float a = arow[k];
        float4 wv = __ldg((const float4*)(W + k * 64 + 4 * tx));
        s.x = fmaf(a, wv.x, s.x);
        s.y = fmaf(a, wv.y, s.y);
        s.z = fmaf(a, wv.z, s.z);
        s.w = fmaf(a, wv.w, s.w);
    }
    *(float4*)(out + (row0 + ty) * 64 + 4 * tx) = s;
}

// ---------------------------------------------------------------------------
extern "C" void kernel_launch(void* const* d_in, const int* in_sizes, int n_in,
                              void* d_out, int out_size)
{
    const float* queries = (const float*)d_in[0];
    const float* values  = (const float*)d_in[1];
    const float* U_re    = (const float*)d_in[2];
    const float* U_im    = (const float*)d_in[3];
    const float* bias    = (const float*)d_in[4];
    const float* theta1  = (const float*)d_in[5];
    const float* phi1    = (const float*)d_in[6];
    const float* theta2  = (const float*)d_in[7];
    const float* phi2    = (const float*)d_in[8];
    const float* omega   = (const float*)d_in[9];
    const float* W_dense = (const float*)d_in[10];
    const float* b_dense = (const float*)d_in[11];
    float* out = (float*)d_out;

    k_compute_u<<<256, 256>>>(queries, values, U_re, U_im);
    k_recur<<<256, 512>>>(bias, theta1, phi1, theta2, phi2, omega);
    k_proj<<<64, 256>>>(W_dense, b_dense, out);
}

// round 7
// speedup vs baseline: 1.4043x; 1.1175x over previous
#include <cuda_runtime.h>

#define HEADS 4
#define DIM   64
#define BB    8
#define QQ    128
#define VV    128
#define NN    (BB*QQ)   // 1024

typedef unsigned long long ull;

// Scratch (device globals — no allocation allowed). g_VU has one row of pad
// so the recurrence can prefetch one step past the end unconditionally.
__device__ float2 g_QU[HEADS * NN * DIM];                 // [h][n][j] complex
__device__ float2 g_VU[HEADS * BB * VV * DIM + DIM];      // [h][b][v][j] complex (+pad)
__device__ float  g_acc[NN * HEADS * DIM];                // [n][h*64+j] real

__device__ __forceinline__ float sqrt_apx(float s) {
    float r; asm("sqrt.approx.f32 %0,%1;" : "=f"(r) : "f"(s)); return r;
}
__device__ __forceinline__ float rcp_apx(float s) {
    float r; asm("rcp.approx.f32 %0,%1;" : "=f"(r) : "f"(s)); return r;
}
// f32x2 helpers (real-coefficient packing only; no swaps needed)
__device__ __forceinline__ ull pk(float lo, float hi) {
    ull d; asm("mov.b64 %0,{%1,%2};" : "=l"(d) : "f"(lo), "f"(hi)); return d;
}
__device__ __forceinline__ float lo32(ull a) {
    float x; asm("{ .reg .b32 t; mov.b64 {%0,t},%1; }" : "=f"(x) : "l"(a)); return x;
}
__device__ __forceinline__ float hi32(ull a) {
    float x; asm("{ .reg .b32 t; mov.b64 {t,%0},%1; }" : "=f"(x) : "l"(a)); return x;
}
__device__ __forceinline__ ull fma2(ull a, ull b, ull c) {
    ull d; asm("fma.rn.f32x2 %0,%1,%2,%3;" : "=l"(d) : "l"(a), "l"(b), "l"(c)); return d;
}
__device__ __forceinline__ ull mul2(ull a, ull b) {
    ull d; asm("mul.rn.f32x2 %0,%1,%2;" : "=l"(d) : "l"(a), "l"(b)); return d;
}
__device__ __forceinline__ ull add2(ull a, ull b) {
    ull d; asm("add.rn.f32x2 %0,%1,%2;" : "=l"(d) : "l"(a), "l"(b)); return d;
}

// ---------------------------------------------------------------------------
// Kernel 1 (tiled GEMM): for part p (0:queries->g_QU, 1:values->g_VU), head h,
// 32-row tile:  out[row, j] = sum_k x[row,k] * U[h, p*64+k, j]  (complex)
// ---------------------------------------------------------------------------
__global__ void __launch_bounds__(256) k_compute_u(
    const float* __restrict__ q,      // [1024,64]
    const float* __restrict__ vals,   // [1024,64]
    const float* __restrict__ Ure,    // [4,128,64]
    const float* __restrict__ Uim)
{
    __shared__ float x_s[32 * 64];    // [r][k]
    __shared__ float ur_s[64 * 64];   // [k][j]
    __shared__ float ui_s[64 * 64];

    int t    = threadIdx.x;
    int tile = blockIdx.x & 31;
    int p    = (blockIdx.x >> 5) & 1;
    int h    = blockIdx.x >> 6;

    const float4* src4 = (const float4*)((p == 0 ? q : vals) + tile * 32 * 64);
    float4* xs4 = (float4*)x_s;
    #pragma unroll
    for (int i = 0; i < 2; i++) xs4[t + 256 * i] = __ldg(src4 + t + 256 * i);

    const float4* ur4 = (const float4*)(Ure + h * 8192 + p * 4096);
    const float4* ui4 = (const float4*)(Uim + h * 8192 + p * 4096);
    float4* urs4 = (float4*)ur_s;
    float4* uis4 = (float4*)ui_s;
    #pragma unroll
    for (int i = 0; i < 4; i++) {
        urs4[t + 256 * i] = __ldg(ur4 + t + 256 * i);
        uis4[t + 256 * i] = __ldg(ui4 + t + 256 * i);
    }
    __syncthreads();

    int j0 = t & 31, j1 = j0 + 32, rg = t >> 5;

    float a0r[4], a0i[4], a1r[4], a1i[4];
    #pragma unroll
    for (int i = 0; i < 4; i++) { a0r[i] = a0i[i] = a1r[i] = a1i[i] = 0.f; }

    #pragma unroll 8
    for (int k = 0; k < 64; k++) {
        float u0r = ur_s[k * 64 + j0];
        float u1r = ur_s[k * 64 + j1];
        float u0i = ui_s[k * 64 + j0];
        float u1i = ui_s[k * 64 + j1];
        #pragma unroll
        for (int i = 0; i < 4; i++) {
            float xv = x_s[(rg * 4 + i) * 64 + k];
            a0r[i] = fmaf(xv, u0r, a0r[i]);
            a0i[i] = fmaf(xv, u0i, a0i[i]);
            a1r[i] = fmaf(xv, u1r, a1r[i]);
            a1i[i] = fmaf(xv, u1i, a1i[i]);
        }
    }

    float2* dst = (p == 0 ? g_QU : g_VU) + (size_t)h * NN * DIM + (size_t)tile * 32 * DIM;
    #pragma unroll
    for (int i = 0; i < 4; i++) {
        int row = rg * 4 + i;
        dst[row * DIM + j0] = make_float2(a0r[i], a0i[i]);
        dst[row * DIM + j1] = make_float2(a1r[i], a1i[i]);
    }
}

// ---------------------------------------------------------------------------
// Kernel 2: EUNN+modrelu recurrence. One warp per (h, n). Lane l owns complex
// elems 2l (A) and 2l+1 (B), state packed (re,im) in f32x2 pairs.
// Folded form (nA never materialized):
//   tA = c1*A - s1*B            (packed f32x2, real coeffs)
//   nB = s1*A + c1*B            (packed f32x2, real coeffs)
//   zB = P*nB - Q*xd + in,   P = E*c2,  Q = E*s2*e1_{l+1},  E = e^{i(wB+phi2_l)}
//   zA = G'*tA + F*xu + in,  G' = e^{i wA}*c2p*e1,  F = e^{i wA}*s2p
//   xd = tA of lane l+1, xu = nB of lane l-1
//   modrelu: sc = max(1 + (b-1e-5)*rcp(|z|+1e-5), 0);  h = z*sc
// ---------------------------------------------------------------------------
__global__ void __launch_bounds__(512) k_recur(
    const float* __restrict__ bias,   // [4,64]
    const float* __restrict__ th1,    // [4,32]
    const float* __restrict__ ph1,    // [4,32]
    const float* __restrict__ th2,    // [4,31]
    const float* __restrict__ ph2,    // [4,31]
    const float* __restrict__ om)     // [4,64]
{
    const unsigned FULL = 0xffffffffu;
    int w = (blockIdx.x * blockDim.x + threadIdx.x) >> 5;   // 0..4095
    int l = threadIdx.x & 31;
    int h = w >> 10;
    int n = w & (NN - 1);
    int b = n >> 7;

    // layer-1 constants
    float c1, s1, e1r, e1i;
    sincosf(th1[h * 32 + l], &s1, &c1);
    sincosf(ph1[h * 32 + l], &e1i, &e1r);

    // layer-2 constants (pair l couples elems 2l+1, 2l+2)
    float c2 = 1.f, s2 = 0.f, p2 = 0.f;
    if (l < 31) {
        sincosf(th2[h * 31 + l], &s2, &c2);
        p2 = ph2[h * 31 + l];
    }
    float c2p = 1.f, s2p = 0.f;
    if (l > 0) sincosf(th2[h * 31 + l - 1], &s2p, &c2p);

    float omA = om[h * 64 + 2 * l];
    float omB = om[h * 64 + 2 * l + 1];

    // e1 of lane l+1 (lane 31: unused, s2=0 kills it)
    float e1nr = __shfl_down_sync(FULL, e1r, 1);
    float e1ni = __shfl_down_sync(FULL, e1i, 1);

    // E = e^{i(omB + phi2_l)}
    float Er, Ei;
    sincosf(omB + p2, &Ei, &Er);
    // P = E*c2
    float Pr = c2 * Er, Pi = c2 * Ei;
    // Q = E*s2*e1_next
    float Qr = s2 * (Er * e1nr - Ei * e1ni);
    float Qi = s2 * (Er * e1ni + Ei * e1nr);
    // G' = e^{i omA} * c2p * e1 ; F = e^{i omA} * s2p
    float cA_, sA_;
    sincosf(omA, &sA_, &cA_);
    float Gr = c2p * (cA_ * e1r - sA_ * e1i);
    float Gi = c2p * (cA_ * e1i + sA_ * e1r);
    float Fr = s2p * cA_, Fi = s2p * sA_;

    float bAp = bias[h * 64 + 2 * l]     - 1e-5f;
    float bBp = bias[h * 64 + 2 * l + 1] - 1e-5f;

    // packed real-coefficient constants for layer 1
    ull c1p  = pk(c1, c1);
    ull s1p  = pk(s1, s1);
    ull ns1p = pk(-s1, -s1);

    // per-warp constant input (QU) and per-step VU stream
    float4 qu = __ldg((const float4*)&g_QU[(h * NN + n) * DIM + 2 * l]);
    ull quA2 = pk(qu.x, qu.y);
    ull quB2 = pk(qu.z, qu.w);
    const float4* vup = (const float4*)&g_VU[((h * BB + b) * VV) * DIM + 2 * l];

    ull A2 = 0ull, B2 = 0ull;   // (re, im) packed state

    float4 vu = __ldg(vup); vup += DIM / 2;   // prefetch step 0

    #pragma unroll 4
    for (int v = 0; v < VV; v++) {
        float4 vun = __ldg(vup); vup += DIM / 2;   // prefetch next (pad covers v=127)

        // input term (packed adds)
        ull inA2 = add2(quA2, pk(vu.x, vu.y));
        ull inB2 = add2(quB2, pk(vu.z, vu.w));

        // layer 1 (packed, real coefficients)
        ull tA2 = fma2(c1p, A2, mul2(ns1p, B2));   // c1*A - s1*B  (re,im)
        ull nB2 = fma2(s1p, A2, mul2(c1p, B2));    // s1*A + c1*B  (re,im)

        // cross-lane exchange (64-bit shfl = 2 SHFL each)
        ull xu2 = __shfl_up_sync(FULL, nB2, 1);    // nB of lane l-1
        ull xd2 = __shfl_down_sync(FULL, tA2, 1);  // tA of lane l+1

        float nBr = lo32(nB2), nBi = hi32(nB2);
        float tAr = lo32(tA2), tAi = hi32(tA2);
        float xur = lo32(xu2), xui = hi32(xu2);
        float xdr = lo32(xd2), xdi = hi32(xd2);
        float inAr = lo32(inA2), inAi = hi32(inA2);
        float inBr = lo32(inB2), inBi = hi32(inB2);

        // B path: zB = P*nB - Q*xd + in   (complex, folded)
        float zBr = fmaf(Pr, nBr, fmaf(-Pi, nBi, fmaf(-Qr, xdr, fmaf( Qi, xdi, inBr))));
        float zBi = fmaf(Pr, nBi, fmaf( Pi, nBr, fmaf(-Qr, xdi, fmaf(-Qi, xdr, inBi))));

        // A path: zA = G'*tA + F*xu + in  (complex, folded)
        float zAr = fmaf(Gr, tAr, fmaf(-Gi, tAi, fmaf(Fr, xur, fmaf(-Fi, xui, inAr))));
        float zAi = fmaf(Gr, tAi, fmaf( Gi, tAr, fmaf(Fr, xui, fmaf( Fi, xur, inAi))));

        // modrelu A
        float sA = fmaf(zAi, zAi, zAr * zAr);
        float mA = sqrt_apx(sA);
        float rA = rcp_apx(mA + 1e-5f);
        float scA = fmaxf(fmaf(bAp, rA, 1.0f), 0.0f);
        A2 = pk(zAr * scA, zAi * scA);

        // modrelu B
        float sB = fmaf(zBi, zBi, zBr * zBr);
        float mB = sqrt_apx(sB);
        float rB = rcp_apx(mB + 1e-5f);
        float scB = fmaxf(fmaf(bBp, rB, 1.0f), 0.0f);
        B2 = pk(zBr * scB, zBi * scB);

        vu = vun;
    }

    float2* accp = (float2*)&g_acc[n * (HEADS * DIM) + h * DIM + 2 * l];
    *accp = make_float2(lo32(A2), lo32(B2));
}

// ---------------------------------------------------------------------------
// Kernel 3: y = acc @ W + b   ([1024,256] @ [256,64])
// ---------------------------------------------------------------------------
#define AST 264
__global__ void __launch_bounds__(256) k_proj(
    const float* __restrict__ W,    // [256,64]
    const float* __restrict__ bd,   // [64]
    float* __restrict__ out)        // [1024,64]
{
    __shared__ float a_s[16 * AST];
    int t = threadIdx.x;
    int row0 = blockIdx.x * 16;

    const float4* g4 = (const float4*)(g_acc + row0 * 256);
    #pragma unroll
    for (int i = 0; i < 4; i++) {
        int g = t + 256 * i;
        int r = g >> 6, c4 = g & 63;
        *(float4*)&a_s[r * AST + c4 * 4] = __ldg(g4 + g);
    }
    __syncthreads();

    int tx = t & 15, ty = t >> 4;
    float4 s = __ldg((const float4*)(bd + 4 * tx));
    const float* arow = a_s + ty * AST;

    #pragma unroll 4
    for (int k = 0; k < 256; k++) {
        float a = arow[k];
        float4 wv = __ldg((const float4*)(W + k * 64 + 4 * tx));
        s.x = fmaf(a, wv.x, s.x);
        s.y = fmaf(a, wv.y, s.y);
        s.z = fmaf(a, wv.z, s.z);
        s.w = fmaf(a, wv.w, s.w);
    }
    *(float4*)(out + (row0 + ty) * 64 + 4 * tx) = s;
}

// ---------------------------------------------------------------------------
extern "C" void kernel_launch(void* const* d_in, const int* in_sizes, int n_in,
                              void* d_out, int out_size)
{
    const float* queries = (const float*)d_in[0];
    const float* values  = (const float*)d_in[1];
    const float* U_re    = (const float*)d_in[2];
    const float* U_im    = (const float*)d_in[3];
    const float* bias    = (const float*)d_in[4];
    const float* theta1  = (const float*)d_in[5];
    const float* phi1    = (const float*)d_in[6];
    const float* theta2  = (const float*)d_in[7];
    const float* phi2    = (const float*)d_in[8];
    const float* omega   = (const float*)d_in[9];
    const float* W_dense = (const float*)d_in[10];
    const float* b_dense = (const float*)d_in[11];
    float* out = (float*)d_out;

    k_compute_u<<<256, 256>>>(queries, values, U_re, U_im);
    k_recur<<<256, 512>>>(bias, theta1, phi1, theta2, phi2, omega);
    k_proj<<<64, 256>>>(W_dense, b_dense, out);
}